// round 4
// baseline (speedup 1.0000x reference)
#include <cuda_runtime.h>
#include <cuda_bf16.h>
#include <cstdint>

// out = (v_reset > 0.5) where v_reset = v*(1-spike1) <= 0.5 always
// (reset-to-0 if above threshold, else unchanged and <= thr; strict compare).
// Output is identically ZERO for all inputs -> pure 134MB zero-fill of d_out.
//
// R1: 1x16B store/thread          -> kernel 20.19us (6.65 TB/s)
// R2: 8x16B/thread, .cs           -> 20.32us NEUTRAL (not wave/issue bound)
// R3: evict_last on 16B stores    -> ptxas: modifier needs 256-bit stores
// R4: st.global.L2::evict_last.v8.b32 (32B stores). 134MB output vs ~126MB
//     L2 -> buffer stays L2-resident across graph replays; steady-state DRAM
//     writeback drops from 134MB to ~8MB churn. If R1/R2 were DRAM-write
//     bound, binder moves to the LTS write cap -> predict ~13-15us kernel.

#define ST_PER_THREAD 8   // 8 x 32B = 256B per thread

__global__ void __launch_bounds__(256) zero_fill_el_v8(float* __restrict__ out,
                                                       long long n8) {
    // index in units of 8-float (32B) groups
    long long base = (long long)blockIdx.x * (256 * ST_PER_THREAD) + threadIdx.x;
#pragma unroll
    for (int k = 0; k < ST_PER_THREAD; k++) {
        long long i = base + (long long)k * 256;
        if (i < n8) {
            float* p = out + i * 8;
            asm volatile(
                "st.global.L2::evict_last.v8.f32 [%0], "
                "{%1, %2, %3, %4, %5, %6, %7, %8};"
                :: "l"(p),
                   "f"(0.0f), "f"(0.0f), "f"(0.0f), "f"(0.0f),
                   "f"(0.0f), "f"(0.0f), "f"(0.0f), "f"(0.0f)
                : "memory");
        }
    }
}

__global__ void zero_fill_tail(float* __restrict__ out,
                               long long start, long long n) {
    long long i = start + (long long)blockIdx.x * blockDim.x + threadIdx.x;
    if (i < n) out[i] = 0.f;
}

extern "C" void kernel_launch(void* const* d_in, const int* in_sizes, int n_in,
                              void* d_out, int out_size) {
    (void)d_in; (void)in_sizes; (void)n_in;

    long long n = (long long)out_size;   // 33,554,432 floats
    long long n8 = n / 8;                // 4,194,304 32B groups

    const int threads = 256;
    long long per_block = (long long)threads * ST_PER_THREAD;
    long long blocks = (n8 + per_block - 1) / per_block;   // 2048
    if (blocks > 0) {
        zero_fill_el_v8<<<(unsigned)blocks, threads>>>((float*)d_out, n8);
    }

    long long rem_start = n8 * 8;
    if (n - rem_start > 0) {
        zero_fill_tail<<<1, 256>>>((float*)d_out, rem_start, n);
    }
}

// round 5
// speedup vs baseline: 1.4576x; 1.4576x over previous
#include <cuda_runtime.h>
#include <cuda_bf16.h>
#include <cstdint>

// out = (v_reset > 0.5) where v_reset = v*(1-spike1) <= 0.5 always
// (reset-to-0 above threshold, else unchanged <= thr; strict compare).
// Output is identically ZERO for all inputs -> pure 134MB zero-fill of d_out.
//
// History:
//  R1: 1x16B STG/thread            kernel 20.19us, dur 23.14  (6.65 TB/s)
//  R2: 8x16B/thread + .cs          kernel 20.32us  NEUTRAL
//  R4: 32B evict_last stores       kernel 31.20us  REGRESSED (L2 policy
//      thrash: 134MB evict_last footprint > 126MB L2)
// Model: all SM-store variants pin at ~6.65 TB/s = LTS write cap
// (~6300 B/cyc, path-independent). 20.2us kernel is the SM-path floor.
//
// R5: graph memset node (cudaMemsetAsync during capture -> 1 memset node;
// legal: no allocation, analogous to the sanctioned cudaMemcpyAsync D2D).
// Tests the one remaining hardware path (driver fill / CE) + lower node
// overhead. Predict neutral-to-slightly-better; revert to R1 if worse.

__global__ void zero_fill_tail(float* __restrict__ out,
                               long long start, long long n) {
    long long i = start + (long long)blockIdx.x * blockDim.x + threadIdx.x;
    if (i < n) out[i] = 0.f;
}

extern "C" void kernel_launch(void* const* d_in, const int* in_sizes, int n_in,
                              void* d_out, int out_size) {
    (void)d_in; (void)in_sizes; (void)n_in;

    size_t bytes = (size_t)out_size * sizeof(float);   // 134,217,728 bytes
    // Single memset node on the capture (default) stream.
    cudaMemsetAsync(d_out, 0, bytes, 0);
}